// round 9
// baseline (speedup 1.0000x reference)
#include <cuda_runtime.h>
#include <stdint.h>
#include <math.h>

#define BATCH 4
#define SEQ   2048
#define DMODEL 512
#define NHEAD 8
#define DHEAD 64
#define MROWS (BATCH*SEQ)          // 8192
#define DKU   (DMODEL/2)           // 256 uints (bf16 pairs) per row
#define NEG_INF_F (-4294967295.0f) // -2^32+1
#define LN_EPS_F 1e-8f
#define UPAD 36                    // padded smem row stride in uint32 (bank-clean)

// ---- scratch (no allocs allowed) ----
__device__ uint32_t g_inb[3u*MROWS*DKU];   // bf16-packed inputs q|k|v
__device__ uint32_t g_Wb[3u*DMODEL*DKU];   // bf16 W transposed [n][kpair], q|k|v
__device__ uint32_t g_Pq[MROWS*DKU];       // projected Q (bf16 pairs)
__device__ uint32_t g_Pk[MROWS*DKU];
__device__ uint32_t g_Pv[MROWS*DKU];
__device__ float    g_att[MROWS*DMODEL];
__device__ float    g_qmask[MROWS];
__device__ float    g_kmask[MROWS];

// pack two fp32 -> bf16x2 (lo in low half)
__device__ __forceinline__ uint32_t pack_bf16(float lo, float hi) {
    uint32_t r;
    asm("cvt.rn.bf16x2.f32 %0, %1, %2;" : "=r"(r) : "f"(hi), "f"(lo));
    return r;
}

__device__ __forceinline__ uint32_t mul_bf16x2(uint32_t a, uint32_t b) {
    uint32_t r;
    asm("mul.rn.bf16x2 %0, %1, %2;" : "=r"(r) : "r"(a), "r"(b));
    return r;
}

// D += A @ B  (m16n8k16 bf16, fp32 accum; A row-major, B col-major)
#define MMA_BF16(d, a, b0, b1)                                              \
    asm volatile(                                                           \
        "mma.sync.aligned.m16n8k16.row.col.f32.bf16.bf16.f32 "              \
        "{%0,%1,%2,%3}, {%4,%5,%6,%7}, {%8,%9}, {%0,%1,%2,%3};"             \
        : "+f"((d)[0]), "+f"((d)[1]), "+f"((d)[2]), "+f"((d)[3])            \
        : "r"((a)[0]), "r"((a)[1]), "r"((a)[2]), "r"((a)[3]),               \
          "r"(b0), "r"(b1))

__device__ __forceinline__ void cp16(uint32_t* s, const uint32_t* g) {
    uint32_t sa = (uint32_t)__cvta_generic_to_shared(s);
    asm volatile("cp.async.ca.shared.global [%0], [%1], 16;" :: "r"(sa), "l"(g));
}
#define CP_COMMIT() asm volatile("cp.async.commit_group;")
#define CP_WAIT1()  asm volatile("cp.async.wait_group 1;")

// ============================================================
// convert inputs fp32 -> bf16 pairs + row masks (fused)
// ============================================================
__global__ void convert_in_kernel(const float* __restrict__ q,
                                  const float* __restrict__ k,
                                  const float* __restrict__ v) {
    int row = blockIdx.x;
    int tid = threadIdx.x;
    size_t off = (size_t)row * DMODEL + tid * 4;
    size_t uoff = (size_t)row * DKU + tid * 2;

    float4 vq = *(const float4*)&q[off];
    float4 vk = *(const float4*)&k[off];
    float4 vv = *(const float4*)&v[off];
    uint2 pq, pk, pv;
    pq.x = pack_bf16(vq.x, vq.y); pq.y = pack_bf16(vq.z, vq.w);
    pk.x = pack_bf16(vk.x, vk.y); pk.y = pack_bf16(vk.z, vk.w);
    pv.x = pack_bf16(vv.x, vv.y); pv.y = pack_bf16(vv.z, vv.w);
    *(uint2*)&g_inb[uoff]                           = pq;
    *(uint2*)&g_inb[(size_t)MROWS * DKU + uoff]     = pk;
    *(uint2*)&g_inb[(size_t)2 * MROWS * DKU + uoff] = pv;

    float sq = vq.x + vq.y + vq.z + vq.w;
    float sk = vk.x + vk.y + vk.z + vk.w;
    #pragma unroll
    for (int o = 16; o; o >>= 1) {
        sq += __shfl_xor_sync(0xffffffffu, sq, o);
        sk += __shfl_xor_sync(0xffffffffu, sk, o);
    }
    __shared__ float bq[4], bk[4];
    if ((tid & 31) == 0) { bq[tid >> 5] = sq; bk[tid >> 5] = sk; }
    __syncthreads();
    if (tid == 0) {
        float tq = bq[0] + bq[1] + bq[2] + bq[3];
        float tk = bk[0] + bk[1] + bk[2] + bk[3];
        g_qmask[row] = (tq != 0.f) ? 1.f : 0.f;
        g_kmask[row] = (tk != 0.f) ? 1.f : 0.f;
    }
}

// ============================================================
// convert W -> transposed bf16 pairs: g_Wb[z][n][kpair]
// ============================================================
__global__ void convert_w_kernel(const float* __restrict__ Wq,
                                 const float* __restrict__ Wk,
                                 const float* __restrict__ Wv) {
    const float* W = (blockIdx.z == 0) ? Wq : (blockIdx.z == 1) ? Wk : Wv;
    __shared__ float T[64][65];   // T[n][k]
    int n0 = blockIdx.x * 64, k0 = blockIdx.y * 64;
    int tid = threadIdx.x;
    #pragma unroll
    for (int it = 0; it < 16; it++) {
        int lin = tid + it * 256;
        int r = lin >> 6, c = lin & 63;           // r=k, c=n
        T[c][r] = W[(size_t)(k0 + r) * DMODEL + n0 + c];
    }
    __syncthreads();
    uint32_t* out = g_Wb + (size_t)blockIdx.z * DMODEL * DKU;
    #pragma unroll
    for (int it = 0; it < 8; it++) {
        int lin = tid + it * 256;
        int n = lin >> 5, kp = lin & 31;
        out[(size_t)(n0 + n) * DKU + (k0 >> 1) + kp] =
            pack_bf16(T[n][2 * kp], T[n][2 * kp + 1]);
    }
}

// ============================================================
// fused projections: C = relu(A @ W + b), bf16 in/out, fp32 accum
// grid (N/128, M/128, 3), block 256, K-chunk 64, cp.async dbl-buffered
// ============================================================
__global__ void __launch_bounds__(256)
gemm_relu_bf16(const float* __restrict__ biasq,
               const float* __restrict__ biask,
               const float* __restrict__ biasv) {
    int z = blockIdx.z;
    const uint32_t* Ab = g_inb + (size_t)z * MROWS * DKU;
    const uint32_t* Wb = g_Wb + (size_t)z * DMODEL * DKU;
    const float* bias = (z == 0) ? biasq : (z == 1) ? biask : biasv;
    uint32_t* C = (z == 0) ? g_Pq : (z == 1) ? g_Pk : g_Pv;

    extern __shared__ uint32_t sm[];
    uint32_t* Abuf = sm;                    // 2 x 128 x UPAD
    uint32_t* Wbuf = sm + 2 * 128 * UPAD;   // 2 x 128 x UPAD

    int tid = threadIdx.x;
    int w = tid >> 5, lane = tid & 31;
    int g = lane >> 2, tg = lane & 3;
    int wm = w >> 1, wn = w & 1;
    int m0 = blockIdx.y * 128, n0 = blockIdx.x * 128;
    int mw = wm * 32;

    float acc[16][4];
    #pragma unroll
    for (int i = 0; i < 16; i++)
        #pragma unroll
        for (int j = 0; j < 4; j++) acc[i][j] = 0.f;

    auto stage = [&](int buf, int k0) {
        const uint32_t* Ag = Ab + (size_t)m0 * DKU + (k0 >> 1);
        const uint32_t* Wg = Wb + (size_t)n0 * DKU + (k0 >> 1);
        uint32_t* Ad = Abuf + buf * 128 * UPAD;
        uint32_t* Wd = Wbuf + buf * 128 * UPAD;
        #pragma unroll
        for (int it = 0; it < 4; it++) {
            int lin = tid + it * 256;
            int r = lin >> 3, c = (lin & 7) << 2;
            cp16(Ad + r * UPAD + c, Ag + (size_t)r * DKU + c);
            cp16(Wd + r * UPAD + c, Wg + (size_t)r * DKU + c);
        }
    };

    stage(0, 0);
    CP_COMMIT();

    for (int i = 0; i < 8; i++) {
        if (i + 1 < 8) stage((i + 1) & 1, (i + 1) * 64);
        CP_COMMIT();
        CP_WAIT1();
        __syncthreads();
        const uint32_t* Ap = Abuf + (i & 1) * 128 * UPAD;
        const uint32_t* Wp = Wbuf + (i & 1) * 128 * UPAD;
        #pragma unroll
        for (int ks = 0; ks < 4; ks++) {
            int cb = ks * 8 + tg;
            uint32_t a0[4], a1[4];
            a0[0] = Ap[(mw + g) * UPAD + cb];
            a0[1] = Ap[(mw + g + 8) * UPAD + cb];
            a0[2] = Ap[(mw + g) * UPAD + cb + 4];
            a0[3] = Ap[(mw + g + 8) * UPAD + cb + 4];
            a1[0] = Ap[(mw + 16 + g) * UPAD + cb];
            a1[1] = Ap[(mw + 24 + g) * UPAD + cb];
            a1[2] = Ap[(mw + 16 + g) * UPAD + cb + 4];
            a1[3] = Ap[(mw + 24 + g) * UPAD + cb + 4];
            #pragma unroll
            for (int nb = 0; nb < 8; nb++) {
                uint32_t b0 = Wp[(wn * 64 + nb * 8 + g) * UPAD + cb];
                uint32_t b1 = Wp[(wn * 64 + nb * 8 + g) * UPAD + cb + 4];
                MMA_BF16(acc[nb], a0, b0, b1);
                MMA_BF16(acc[8 + nb], a1, b0, b1);
            }
        }
        __syncthreads();
    }

    #pragma unroll
    for (int mt = 0; mt < 2; mt++) {
        int r0 = m0 + mw + mt * 16 + g;
        int r1 = r0 + 8;
        #pragma unroll
        for (int nb = 0; nb < 8; nb++) {
            int c = n0 + wn * 64 + nb * 8 + 2 * tg;
            float b0v = bias[c], b1v = bias[c + 1];
            const float* ac = acc[mt * 8 + nb];
            uint32_t cu = (c >> 1);
            C[(size_t)r0 * DKU + cu] =
                pack_bf16(fmaxf(ac[0] + b0v, 0.f), fmaxf(ac[1] + b1v, 0.f));
            C[(size_t)r1 * DKU + cu] =
                pack_bf16(fmaxf(ac[2] + b0v, 0.f), fmaxf(ac[3] + b1v, 0.f));
        }
    }
}

// ============================================================
// flash attention, bf16 m16n8k16 mma, fp32 softmax
// BQ=128 (8 warps x 16 q-rows), BK=64, dh=64
// grid: (SEQ/128, NHEAD*BATCH), block 256, 2 CTAs/SM
// dyn smem (uint32): Kp[64][UPAD] | Vp[64][UPAD] | Pp[128][UPAD]
// ============================================================
__global__ void __launch_bounds__(256, 2)
attn_bf16_kernel() {
    extern __shared__ uint32_t sm[];
    uint32_t* Kp = sm;                 // K [key][kpair]
    uint32_t* Vp = sm + 64 * UPAD;     // V [d][keypair]
    uint32_t* Pp = sm + 128 * UPAD;    // P/Q [q][keypair] (warp-private rows)
    __shared__ float kms[64];

    int tid = threadIdx.x;
    int w = tid >> 5, lane = tid & 31;
    int g = lane >> 2, tg = lane & 3;
    int head = blockIdx.y >> 2, b = blockIdx.y & 3;
    int q0 = blockIdx.x * 128;
    int mw = w * 16;
    int hoff = head * 32;   // head offset in uints

    const uint32_t* Qb = g_Pq + (size_t)b * SEQ * DKU + hoff;
    const uint32_t* Kb = g_Pk + (size_t)b * SEQ * DKU + hoff;
    const uint32_t* Vb = g_Pv + (size_t)b * SEQ * DKU + hoff;

    // ---- stage Q pre-scaled by 1/8 (exact bf16 exponent shift) ----
    const uint32_t SCL = 0x3E003E00u;   // bf16x2 {0.125, 0.125}
    #pragma unroll
    for (int it = 0; it < 4; it++) {
        int lin = tid + it * 256;
        int r = lin >> 3, c = (lin & 7) << 2;
        uint4 v = *(const uint4*)&Qb[(size_t)(q0 + r) * DKU + c];
        v.x = mul_bf16x2(v.x, SCL); v.y = mul_bf16x2(v.y, SCL);
        v.z = mul_bf16x2(v.z, SCL); v.w = mul_bf16x2(v.w, SCL);
        *(uint4*)&Pp[r * UPAD + c] = v;
    }
    __syncthreads();
    uint32_t Qa[4][4];
    #pragma unroll
    for (int ks = 0; ks < 4; ks++) {
        int cb = ks * 8 + tg;
        Qa[ks][0] = Pp[(mw + g) * UPAD + cb];
        Qa[ks][1] = Pp[(mw + g + 8) * UPAD + cb];
        Qa[ks][2] = Pp[(mw + g) * UPAD + cb + 4];
        Qa[ks][3] = Pp[(mw + g + 8) * UPAD + cb + 4];
    }

    float O[8][4];
    #pragma unroll
    for (int i = 0; i < 8; i++)
        #pragma unroll
        for (int j = 0; j < 4; j++) O[i][j] = 0.f;
    float mr[2] = {-3.0e38f, -3.0e38f};
    float lr[2] = {0.f, 0.f};

    for (int kt = 0; kt < SEQ; kt += 64) {
        // stage K (direct uint4 copies)
        #pragma unroll
        for (int it = 0; it < 2; it++) {
            int lin = tid + it * 256;
            int r = lin >> 3, c = (lin & 7) << 2;
            *(uint4*)&Kp[r * UPAD + c] = *(const uint4*)&Kb[(size_t)(kt + r) * DKU + c];
        }
        // stage V transposed [d][keypair] via prmt
        #pragma unroll
        for (int it = 0; it < 8; it++) {
            int lin = tid + it * 256;
            int kp = lin >> 6, d = lin & 63;
            uint32_t a = Vb[(size_t)(kt + 2 * kp) * DKU + (d >> 1)];
            uint32_t bb = Vb[(size_t)(kt + 2 * kp + 1) * DKU + (d >> 1)];
            Vp[d * UPAD + kp] = __byte_perm(a, bb, (d & 1) ? 0x7632 : 0x5410);
        }
        if (tid < 64) kms[tid] = g_kmask[b * SEQ + kt + tid];
        __syncthreads();

        // ---- S = (Q/8) @ K^T : per warp 16 x 64 ----
        float Sc[8][4];
        #pragma unroll
        for (int i = 0; i < 8; i++)
            #pragma unroll
            for (int j = 0; j < 4; j++) Sc[i][j] = 0.f;
        #pragma unroll
        for (int ks = 0; ks < 4; ks++) {
            int cb = ks * 8 + tg;
            #pragma unroll
            for (int nb = 0; nb < 8; nb++) {
                uint32_t b0 = Kp[(nb * 8 + g) * UPAD + cb];
                uint32_t b1 = Kp[(nb * 8 + g) * UPAD + cb + 4];
                MMA_BF16(Sc[nb], Qa[ks], b0, b1);
            }
        }

        // ---- key mask + running row max (2 rows/lane) ----
        float mx0 = -3.0e38f, mx1 = -3.0e38f;
        #pragma unroll
        for (int nb = 0; nb < 8; nb++) {
            int c = nb * 8 + 2 * tg;
            float km0 = kms[c], km1 = kms[c + 1];
            float* S = Sc[nb];
            S[0] = (km0 != 0.f) ? S[0] : NEG_INF_F;
            S[1] = (km1 != 0.f) ? S[1] : NEG_INF_F;
            S[2] = (km0 != 0.f) ? S[2] : NEG_INF_F;
            S[3] = (km1 != 0.f) ? S[3] : NEG_INF_F;
            mx0 = fmaxf(mx0, fmaxf(S[0], S[1]));
            mx1 = fmaxf(mx1, fmaxf(S[2], S[3]));
        }
        #pragma unroll
        for (int off = 1; off <= 2; off <<= 1) {
            mx0 = fmaxf(mx0, __shfl_xor_sync(0xffffffffu, mx0, off));
            mx1 = fmaxf(mx1, __shfl_xor_sync(0xffffffffu, mx1, off));
        }
        float mn0 = fmaxf(mr[0], mx0), mn1 = fmaxf(mr[1], mx1);
        float al0 = __expf(mr[0] - mn0), al1 = __expf(mr[1] - mn1);
        mr[0] = mn0; mr[1] = mn1;

        // ---- P = exp(S-m): sums + bf16 pack to Pp ----
        float s0 = 0.f, s1 = 0.f;
        {
            int r0 = (mw + g) * UPAD;
            int r1 = (mw + g + 8) * UPAD;
            #pragma unroll
            for (int nb = 0; nb < 8; nb++) {
                float* S = Sc[nb];
                float p0 = __expf(S[0] - mn0);
                float p1 = __expf(S[1] - mn0);
                float p2 = __expf(S[2] - mn1);
                float p3 = __expf(S[3] - mn1);
                s0 += p0 + p1;
                s1 += p2 + p3;
                Pp[r0 + nb * 4 + tg] = pack_bf16(p0, p1);
                Pp[r1 + nb * 4 + tg] = pack_bf16(p2, p3);
            }
        }
        #pragma unroll
        for (int off = 1; off <= 2; off <<= 1) {
            s0 += __shfl_xor_sync(0xffffffffu, s0, off);
            s1 += __shfl_xor_sync(0xffffffffu, s1, off);
        }
        lr[0] = lr[0] * al0 + s0;
        lr[1] = lr[1] * al1 + s1;

        // rescale running O
        #pragma unroll
        for (int nb = 0; nb < 8; nb++) {
            float* o = O[nb];
            o[0] *= al0; o[1] *= al0;
            o[2] *= al1; o[3] *= al1;
        }
        __syncwarp();   // Pp rows warp-private

        // ---- O += P @ V ----
        #pragma unroll
        for (int ks = 0; ks < 4; ks++) {
            int cb = ks * 8 + tg;
            uint32_t a[4];
            a[0] = Pp[(mw + g) * UPAD + cb];
            a[1] = Pp[(mw + g + 8) * UPAD + cb];
            a[2] = Pp[(mw + g) * UPAD + cb + 4];
            a[3] = Pp[(mw + g + 8) * UPAD + cb + 4];
            #pragma unroll
            for (int nb = 0; nb < 8; nb++) {
                uint32_t b0 = Vp[(nb * 8 + g) * UPAD + cb];
                uint32_t b1 = Vp[(nb * 8 + g) * UPAD + cb + 4];
                MMA_BF16(O[nb], a, b0, b1);
            }
        }
        __syncthreads();   // before Kp/Vp/kms reload
    }

    // ---- epilogue: query mask, 1/l, write fp32 ----
    float* Ob = g_att + (size_t)(b * SEQ + q0) * DMODEL + head * DHEAD;
    {
        int r0 = mw + g;
        int r1 = r0 + 8;
        float sc0 = g_qmask[b * SEQ + q0 + r0] / lr[0];
        float sc1 = g_qmask[b * SEQ + q0 + r1] / lr[1];
        #pragma unroll
        for (int nb = 0; nb < 8; nb++) {
            int c = nb * 8 + 2 * tg;
            const float* o = O[nb];
            float2 o0, o1;
            o0.x = o[0] * sc0; o0.y = o[1] * sc0;
            o1.x = o[2] * sc1; o1.y = o[3] * sc1;
            *(float2*)&Ob[(size_t)r0 * DMODEL + c] = o0;
            *(float2*)&Ob[(size_t)r1 * DMODEL + c] = o1;
        }
    }
}

// ============================================================
// residual + LayerNorm (unbiased std, eps added to std)
// ============================================================
__global__ void ln_kernel(const float* __restrict__ queries,
                          const float* __restrict__ gamma,
                          const float* __restrict__ beta,
                          float* __restrict__ out) {
    int row = blockIdx.x;
    int tid = threadIdx.x; // 128
    __shared__ float xs[DMODEL];
    __shared__ float rbuf[4];
    __shared__ float s_mean, s_rstd;
    const float* att = g_att + (size_t)row * DMODEL;
    const float* q   = queries + (size_t)row * DMODEL;

    float s = 0.f;
    for (int i = tid; i < DMODEL; i += 128) {
        float v = att[i] + q[i];
        xs[i] = v;
        s += v;
    }
    #pragma unroll
    for (int off = 16; off; off >>= 1) s += __shfl_xor_sync(0xffffffffu, s, off);
    if ((tid & 31) == 0) rbuf[tid >> 5] = s;
    __syncthreads();
    if (tid == 0) s_mean = (rbuf[0] + rbuf[1] + rbuf[2] + rbuf[3]) * (1.0f / DMODEL);
    __syncthreads();
    float mean = s_mean;
    float v2 = 0.f;
    for (int i = tid; i < DMODEL; i += 128) { float d = xs[i] - mean; v2 += d * d; }
    #pragma unroll
    for (int off = 16; off; off >>= 1) v2 += __shfl_xor_sync(0xffffffffu, v2, off);
    if ((tid & 31) == 0) rbuf[tid >> 5] = v2;
    __syncthreads();
    if (tid == 0) {
        float var = (rbuf[0] + rbuf[1] + rbuf[2] + rbuf[3]) * (1.0f / (DMODEL - 1));
        s_rstd = 1.0f / (sqrtf(var) + LN_EPS_F);
    }
    __syncthreads();
    float rstd = s_rstd;
    for (int i = tid; i < DMODEL; i += 128)
        out[(size_t)row * DMODEL + i] = gamma[i] * (xs[i] - mean) * rstd + beta[i];
}

// ============================================================
extern "C" void kernel_launch(void* const* d_in, const int* in_sizes, int n_in,
                              void* d_out, int out_size) {
    const float* queries = (const float*)d_in[0];
    const float* keys    = (const float*)d_in[1];
    const float* values  = (const float*)d_in[2];
    const float* Wq = (const float*)d_in[3];
    const float* bq = (const float*)d_in[4];
    const float* Wk = (const float*)d_in[5];
    const float* bk = (const float*)d_in[6];
    const float* Wv = (const float*)d_in[7];
    const float* bv = (const float*)d_in[8];
    const float* gamma = (const float*)d_in[9];
    const float* beta  = (const float*)d_in[10];
    float* out = (float*)d_out;

    convert_in_kernel<<<MROWS, 128>>>(queries, keys, values);
    convert_w_kernel<<<dim3(8, 8, 3), 256>>>(Wq, Wk, Wv);

    const int GSMEM = 4 * 128 * UPAD * (int)sizeof(uint32_t); // 73728 B
    cudaFuncSetAttribute(gemm_relu_bf16,
                         cudaFuncAttributeMaxDynamicSharedMemorySize, GSMEM);
    gemm_relu_bf16<<<dim3(DMODEL / 128, MROWS / 128, 3), 256, GSMEM>>>(bq, bk, bv);

    const int ASMEM = 256 * UPAD * (int)sizeof(uint32_t); // 36864 B
    cudaFuncSetAttribute(attn_bf16_kernel,
                         cudaFuncAttributeMaxDynamicSharedMemorySize, ASMEM);
    attn_bf16_kernel<<<dim3(SEQ / 128, NHEAD * BATCH), 256, ASMEM>>>();

    ln_kernel<<<MROWS, 128>>>(queries, gamma, beta, out);
}

// round 12
// speedup vs baseline: 1.0514x; 1.0514x over previous
#include <cuda_runtime.h>
#include <stdint.h>
#include <math.h>

#define BATCH 4
#define SEQ   2048
#define DMODEL 512
#define NHEAD 8
#define DHEAD 64
#define MROWS (BATCH*SEQ)          // 8192
#define DKU   (DMODEL/2)           // 256 uints (bf16 pairs) per row
#define NEG_INF_F (-4294967295.0f) // -2^32+1
#define LN_EPS_F 1e-8f
#define UPAD 36                    // padded smem row stride in uint32 (bank-clean)

// ---- scratch (no allocs allowed) ----
__device__ uint32_t g_inb[3u*MROWS*DKU];   // bf16-packed inputs q|k|v
__device__ uint32_t g_Wb[3u*DMODEL*DKU];   // bf16 W transposed [n][kpair], q|k|v
__device__ uint32_t g_Pq[MROWS*DKU];       // projected Q (bf16 pairs)
__device__ uint32_t g_Pk[MROWS*DKU];
__device__ uint32_t g_Pv[MROWS*DKU];
__device__ float    g_att[MROWS*DMODEL];
__device__ float    g_qmask[MROWS];
__device__ float    g_kmask[MROWS];

// pack two fp32 -> bf16x2 (lo in low half)
__device__ __forceinline__ uint32_t pack_bf16(float lo, float hi) {
    uint32_t r;
    asm("cvt.rn.bf16x2.f32 %0, %1, %2;" : "=r"(r) : "f"(hi), "f"(lo));
    return r;
}

__device__ __forceinline__ uint32_t mul_bf16x2(uint32_t a, uint32_t b) {
    uint32_t r;
    asm("mul.rn.bf16x2 %0, %1, %2;" : "=r"(r) : "r"(a), "r"(b));
    return r;
}

// D += A @ B  (m16n8k16 bf16, fp32 accum; A row-major, B col-major)
#define MMA_BF16(d, a, b0, b1)                                              \
    asm volatile(                                                           \
        "mma.sync.aligned.m16n8k16.row.col.f32.bf16.bf16.f32 "              \
        "{%0,%1,%2,%3}, {%4,%5,%6,%7}, {%8,%9}, {%0,%1,%2,%3};"             \
        : "+f"((d)[0]), "+f"((d)[1]), "+f"((d)[2]), "+f"((d)[3])            \
        : "r"((a)[0]), "r"((a)[1]), "r"((a)[2]), "r"((a)[3]),               \
          "r"(b0), "r"(b1))

#define LDSM4(r0, r1, r2, r3, addr)                                         \
    asm volatile("ldmatrix.sync.aligned.m8n8.x4.shared.b16 "                \
                 "{%0,%1,%2,%3}, [%4];"                                     \
                 : "=r"(r0), "=r"(r1), "=r"(r2), "=r"(r3) : "r"(addr))

__device__ __forceinline__ void cp16(uint32_t* s, const uint32_t* g) {
    uint32_t sa = (uint32_t)__cvta_generic_to_shared(s);
    asm volatile("cp.async.ca.shared.global [%0], [%1], 16;" :: "r"(sa), "l"(g));
}
#define CP_COMMIT() asm volatile("cp.async.commit_group;")
#define CP_WAIT1()  asm volatile("cp.async.wait_group 1;")

// ============================================================
// convert inputs fp32 -> bf16 pairs + row masks (fused)
// ============================================================
__global__ void convert_in_kernel(const float* __restrict__ q,
                                  const float* __restrict__ k,
                                  const float* __restrict__ v) {
    int row = blockIdx.x;
    int tid = threadIdx.x;
    size_t off = (size_t)row * DMODEL + tid * 4;
    size_t uoff = (size_t)row * DKU + tid * 2;

    float4 vq = *(const float4*)&q[off];
    float4 vk = *(const float4*)&k[off];
    float4 vv = *(const float4*)&v[off];
    uint2 pq, pk, pv;
    pq.x = pack_bf16(vq.x, vq.y); pq.y = pack_bf16(vq.z, vq.w);
    pk.x = pack_bf16(vk.x, vk.y); pk.y = pack_bf16(vk.z, vk.w);
    pv.x = pack_bf16(vv.x, vv.y); pv.y = pack_bf16(vv.z, vv.w);
    *(uint2*)&g_inb[uoff]                           = pq;
    *(uint2*)&g_inb[(size_t)MROWS * DKU + uoff]     = pk;
    *(uint2*)&g_inb[(size_t)2 * MROWS * DKU + uoff] = pv;

    float sq = vq.x + vq.y + vq.z + vq.w;
    float sk = vk.x + vk.y + vk.z + vk.w;
    #pragma unroll
    for (int o = 16; o; o >>= 1) {
        sq += __shfl_xor_sync(0xffffffffu, sq, o);
        sk += __shfl_xor_sync(0xffffffffu, sk, o);
    }
    __shared__ float bq[4], bk[4];
    if ((tid & 31) == 0) { bq[tid >> 5] = sq; bk[tid >> 5] = sk; }
    __syncthreads();
    if (tid == 0) {
        float tq = bq[0] + bq[1] + bq[2] + bq[3];
        float tk = bk[0] + bk[1] + bk[2] + bk[3];
        g_qmask[row] = (tq != 0.f) ? 1.f : 0.f;
        g_kmask[row] = (tk != 0.f) ? 1.f : 0.f;
    }
}

// ============================================================
// convert W -> transposed bf16 pairs: g_Wb[z][n][kpair]
// ============================================================
__global__ void convert_w_kernel(const float* __restrict__ Wq,
                                 const float* __restrict__ Wk,
                                 const float* __restrict__ Wv) {
    const float* W = (blockIdx.z == 0) ? Wq : (blockIdx.z == 1) ? Wk : Wv;
    __shared__ float T[64][65];   // T[n][k]
    int n0 = blockIdx.x * 64, k0 = blockIdx.y * 64;
    int tid = threadIdx.x;
    #pragma unroll
    for (int it = 0; it < 16; it++) {
        int lin = tid + it * 256;
        int r = lin >> 6, c = lin & 63;           // r=k, c=n
        T[c][r] = W[(size_t)(k0 + r) * DMODEL + n0 + c];
    }
    __syncthreads();
    uint32_t* out = g_Wb + (size_t)blockIdx.z * DMODEL * DKU;
    #pragma unroll
    for (int it = 0; it < 8; it++) {
        int lin = tid + it * 256;
        int n = lin >> 5, kp = lin & 31;
        out[(size_t)(n0 + n) * DKU + (k0 >> 1) + kp] =
            pack_bf16(T[n][2 * kp], T[n][2 * kp + 1]);
    }
}

// ============================================================
// fused projections: C = relu(A @ W + b), bf16 in/out, fp32 accum
// grid (N/128, M/128, 3), block 256, K-chunk 64, cp.async dbl-buffered
// ============================================================
__global__ void __launch_bounds__(256)
gemm_relu_bf16(const float* __restrict__ biasq,
               const float* __restrict__ biask,
               const float* __restrict__ biasv) {
    int z = blockIdx.z;
    const uint32_t* Ab = g_inb + (size_t)z * MROWS * DKU;
    const uint32_t* Wb = g_Wb + (size_t)z * DMODEL * DKU;
    const float* bias = (z == 0) ? biasq : (z == 1) ? biask : biasv;
    uint32_t* C = (z == 0) ? g_Pq : (z == 1) ? g_Pk : g_Pv;

    extern __shared__ uint32_t sm[];
    uint32_t* Abuf = sm;                    // 2 x 128 x UPAD
    uint32_t* Wbuf = sm + 2 * 128 * UPAD;   // 2 x 128 x UPAD

    int tid = threadIdx.x;
    int w = tid >> 5, lane = tid & 31;
    int g = lane >> 2, tg = lane & 3;
    int wm = w >> 1, wn = w & 1;
    int m0 = blockIdx.y * 128, n0 = blockIdx.x * 128;
    int mw = wm * 32;

    float acc[16][4];
    #pragma unroll
    for (int i = 0; i < 16; i++)
        #pragma unroll
        for (int j = 0; j < 4; j++) acc[i][j] = 0.f;

    auto stage = [&](int buf, int k0) {
        const uint32_t* Ag = Ab + (size_t)m0 * DKU + (k0 >> 1);
        const uint32_t* Wg = Wb + (size_t)n0 * DKU + (k0 >> 1);
        uint32_t* Ad = Abuf + buf * 128 * UPAD;
        uint32_t* Wd = Wbuf + buf * 128 * UPAD;
        #pragma unroll
        for (int it = 0; it < 4; it++) {
            int lin = tid + it * 256;
            int r = lin >> 3, c = (lin & 7) << 2;
            cp16(Ad + r * UPAD + c, Ag + (size_t)r * DKU + c);
            cp16(Wd + r * UPAD + c, Wg + (size_t)r * DKU + c);
        }
    };

    stage(0, 0);
    CP_COMMIT();

    for (int i = 0; i < 8; i++) {
        if (i + 1 < 8) stage((i + 1) & 1, (i + 1) * 64);
        CP_COMMIT();
        CP_WAIT1();
        __syncthreads();
        const uint32_t* Ap = Abuf + (i & 1) * 128 * UPAD;
        const uint32_t* Wp = Wbuf + (i & 1) * 128 * UPAD;
        #pragma unroll
        for (int ks = 0; ks < 4; ks++) {
            int cb = ks * 8 + tg;
            uint32_t a0[4], a1[4];
            a0[0] = Ap[(mw + g) * UPAD + cb];
            a0[1] = Ap[(mw + g + 8) * UPAD + cb];
            a0[2] = Ap[(mw + g) * UPAD + cb + 4];
            a0[3] = Ap[(mw + g + 8) * UPAD + cb + 4];
            a1[0] = Ap[(mw + 16 + g) * UPAD + cb];
            a1[1] = Ap[(mw + 24 + g) * UPAD + cb];
            a1[2] = Ap[(mw + 16 + g) * UPAD + cb + 4];
            a1[3] = Ap[(mw + 24 + g) * UPAD + cb + 4];
            #pragma unroll
            for (int nb = 0; nb < 8; nb++) {
                uint32_t b0 = Wp[(wn * 64 + nb * 8 + g) * UPAD + cb];
                uint32_t b1 = Wp[(wn * 64 + nb * 8 + g) * UPAD + cb + 4];
                MMA_BF16(acc[nb], a0, b0, b1);
                MMA_BF16(acc[8 + nb], a1, b0, b1);
            }
        }
        __syncthreads();
    }

    #pragma unroll
    for (int mt = 0; mt < 2; mt++) {
        int r0 = m0 + mw + mt * 16 + g;
        int r1 = r0 + 8;
        #pragma unroll
        for (int nb = 0; nb < 8; nb++) {
            int c = n0 + wn * 64 + nb * 8 + 2 * tg;
            float b0v = bias[c], b1v = bias[c + 1];
            const float* ac = acc[mt * 8 + nb];
            uint32_t cu = (c >> 1);
            C[(size_t)r0 * DKU + cu] =
                pack_bf16(fmaxf(ac[0] + b0v, 0.f), fmaxf(ac[1] + b1v, 0.f));
            C[(size_t)r1 * DKU + cu] =
                pack_bf16(fmaxf(ac[2] + b0v, 0.f), fmaxf(ac[3] + b1v, 0.f));
        }
    }
}

// ============================================================
// flash attention, bf16 m16n8k16 mma, ldmatrix fragments,
// P kept in registers (C-frag == A-frag layout).
// BQ=128 (8 warps x 16 q-rows), BK=64, dh=64
// grid: (SEQ/128, NHEAD*BATCH), block 256, 2 CTAs/SM
// dyn smem (uint32): Kp[64][UPAD] | Vp[64][UPAD]   (Q staged across both)
// ============================================================
__global__ void __launch_bounds__(256, 2)
attn_bf16_kernel() {
    extern __shared__ uint32_t sm[];
    uint32_t* Kp = sm;                 // K [key][kpair]
    uint32_t* Vp = sm + 64 * UPAD;     // V [d][keypair]
    __shared__ float kms[64];

    int tid = threadIdx.x;
    int w = tid >> 5, lane = tid & 31;
    int g = lane >> 2, tg = lane & 3;
    int l7 = lane & 7, qd = lane >> 3;
    int head = blockIdx.y >> 2, b = blockIdx.y & 3;
    int q0 = blockIdx.x * 128;
    int mw = w * 16;
    int hoff = head * 32;   // head offset in uints

    const uint32_t* Qb = g_Pq + (size_t)b * SEQ * DKU + hoff;
    const uint32_t* Kb = g_Pk + (size_t)b * SEQ * DKU + hoff;
    const uint32_t* Vb = g_Pv + (size_t)b * SEQ * DKU + hoff;

    uint32_t smb = (uint32_t)__cvta_generic_to_shared(sm);

    // ---- stage Q (pre-scaled by 1/8, exact) across Kp|Vp region ----
    const uint32_t SCL = 0x3E003E00u;   // bf16x2 {0.125, 0.125}
    #pragma unroll
    for (int it = 0; it < 4; it++) {
        int lin = tid + it * 256;
        int r = lin >> 3, c = (lin & 7) << 2;
        uint4 v = *(const uint4*)&Qb[(size_t)(q0 + r) * DKU + c];
        v.x = mul_bf16x2(v.x, SCL); v.y = mul_bf16x2(v.y, SCL);
        v.z = mul_bf16x2(v.z, SCL); v.w = mul_bf16x2(v.w, SCL);
        *(uint4*)&sm[r * UPAD + c] = v;
    }
    __syncthreads();

    // A-type ldmatrix lane address: m0=rows g(+0), m1=rows g+8, m2=g +4col, m3=g+8 +4col
    uint32_t qrow = mw + l7 + ((qd & 1) << 3);
    uint32_t qcol = (qd >> 1) << 2;
    uint32_t Qa[4][4];
    #pragma unroll
    for (int ks = 0; ks < 4; ks++)
        LDSM4(Qa[ks][0], Qa[ks][1], Qa[ks][2], Qa[ks][3],
              smb + (qrow * UPAD + ks * 8 + qcol) * 4);
    __syncthreads();   // Q region about to be overwritten by K/V

    // B-type ldmatrix lane offsets: m0=row+0 col+0, m1=row+0 col+4, m2=row+8 col+0, m3=row+8 col+4
    uint32_t brow = l7 + ((qd >> 1) << 3);
    uint32_t bcol = (qd & 1) << 2;
    uint32_t kfb = smb + (brow * UPAD + bcol) * 4;                 // into Kp
    uint32_t vfb = smb + ((64 + brow) * UPAD + bcol) * 4;          // into Vp

    float O[8][4];
    #pragma unroll
    for (int i = 0; i < 8; i++)
        #pragma unroll
        for (int j = 0; j < 4; j++) O[i][j] = 0.f;
    float mr0 = -3.0e38f, mr1 = -3.0e38f;
    float lr0 = 0.f, lr1 = 0.f;

    for (int kt = 0; kt < SEQ; kt += 64) {
        // stage K (direct uint4 copies)
        #pragma unroll
        for (int it = 0; it < 2; it++) {
            int lin = tid + it * 256;
            int r = lin >> 3, c = (lin & 7) << 2;
            *(uint4*)&Kp[r * UPAD + c] = *(const uint4*)&Kb[(size_t)(kt + r) * DKU + c];
        }
        // stage V transposed [d][keypair] via prmt
        #pragma unroll
        for (int it = 0; it < 8; it++) {
            int lin = tid + it * 256;
            int kp = lin >> 6, d = lin & 63;
            uint32_t a = Vb[(size_t)(kt + 2 * kp) * DKU + (d >> 1)];
            uint32_t bb = Vb[(size_t)(kt + 2 * kp + 1) * DKU + (d >> 1)];
            Vp[d * UPAD + kp] = __byte_perm(a, bb, (d & 1) ? 0x7632 : 0x5410);
        }
        if (tid < 64) kms[tid] = g_kmask[b * SEQ + kt + tid];
        __syncthreads();

        // ---- S = (Q/8) @ K^T : per warp 16 x 64, ldmatrix B-frags ----
        float Sc[8][4];
        #pragma unroll
        for (int i = 0; i < 8; i++)
            #pragma unroll
            for (int j = 0; j < 4; j++) Sc[i][j] = 0.f;
        #pragma unroll
        for (int ks = 0; ks < 4; ks++) {
            #pragma unroll
            for (int nbp = 0; nbp < 4; nbp++) {
                uint32_t b0, b1, b2, b3;
                LDSM4(b0, b1, b2, b3, kfb + (nbp * 16 * UPAD + ks * 8) * 4);
                MMA_BF16(Sc[2 * nbp], Qa[ks], b0, b1);
                MMA_BF16(Sc[2 * nbp + 1], Qa[ks], b2, b3);
            }
        }

        // ---- key mask + running row max (2 rows/lane) ----
        float mx0 = -3.0e38f, mx1 = -3.0e38f;
        #pragma unroll
        for (int nb = 0; nb < 8; nb++) {
            int c = nb * 8 + 2 * tg;
            float km0 = kms[c], km1 = kms[c + 1];
            float* S = Sc[nb];
            S[0] = (km0 != 0.f) ? S[0] : NEG_INF_F;
            S[1] = (km1 != 0.f) ? S[1] : NEG_INF_F;
            S[2] = (km0 != 0.f) ? S[2] : NEG_INF_F;
            S[3] = (km1 != 0.f) ? S[3] : NEG_INF_F;
            mx0 = fmaxf(mx0, fmaxf(S[0], S[1]));
            mx1 = fmaxf(mx1, fmaxf(S[2], S[3]));
        }
        #pragma unroll
        for (int off = 1; off <= 2; off <<= 1) {
            mx0 = fmaxf(mx0, __shfl_xor_sync(0xffffffffu, mx0, off));
            mx1 = fmaxf(mx1, __shfl_xor_sync(0xffffffffu, mx1, off));
        }
        float mn0 = fmaxf(mr0, mx0), mn1 = fmaxf(mr1, mx1);
        float al0 = __expf(mr0 - mn0), al1 = __expf(mr1 - mn1);
        mr0 = mn0; mr1 = mn1;

        // ---- P = exp(S-m) packed straight into A-fragments ----
        uint32_t Pa[8][2];
        float s0 = 0.f, s1 = 0.f;
        #pragma unroll
        for (int nb = 0; nb < 8; nb++) {
            float* S = Sc[nb];
            float p0 = __expf(S[0] - mn0);
            float p1 = __expf(S[1] - mn0);
            float p2 = __expf(S[2] - mn1);
            float p3 = __expf(S[3] - mn1);
            s0 += p0 + p1;
            s1 += p2 + p3;
            Pa[nb][0] = pack_bf16(p0, p1);
            Pa[nb][1] = pack_bf16(p2, p3);
        }
        #pragma unroll
        for (int off = 1; off <= 2; off <<= 1) {
            s0 += __shfl_xor_sync(0xffffffffu, s0, off);
            s1 += __shfl_xor_sync(0xffffffffu, s1, off);
        }
        lr0 = lr0 * al0 + s0;
        lr1 = lr1 * al1 + s1;

        // rescale running O
        #pragma unroll
        for (int nb = 0; nb < 8; nb++) {
            float* o = O[nb];
            o[0] *= al0; o[1] *= al0;
            o[2] *= al1; o[3] *= al1;
        }

        // ---- O += P @ V (P A-frags from registers, V via ldmatrix) ----
        #pragma unroll
        for (int j = 0; j < 4; j++) {    // key-blocks of 16
            uint32_t a[4];
            a[0] = Pa[2 * j][0];
            a[1] = Pa[2 * j][1];
            a[2] = Pa[2 * j + 1][0];
            a[3] = Pa[2 * j + 1][1];
            #pragma unroll
            for (int nbp = 0; nbp < 4; nbp++) {
                uint32_t b0, b1, b2, b3;
                LDSM4(b0, b1, b2, b3, vfb + (nbp * 16 * UPAD + j * 8) * 4);
                MMA_BF16(O[2 * nbp], a, b0, b1);
                MMA_BF16(O[2 * nbp + 1], a, b2, b3);
            }
        }
        __syncthreads();   // before Kp/Vp/kms reload
    }

    // ---- epilogue: query mask, 1/l, write fp32 ----
    float* Ob = g_att + (size_t)(b * SEQ + q0) * DMODEL + head * DHEAD;
    {
        int r0 = mw + g;
        int r1 = r0 + 8;
        float sc0 = g_qmask[b * SEQ + q0 + r0] / lr0;
        float sc1 = g_qmask[b * SEQ + q0 + r1] / lr1;
        #pragma unroll
        for (int nb = 0; nb < 8; nb++) {
            int c = nb * 8 + 2 * tg;
            const float* o = O[nb];
            float2 o0, o1;
            o0.x = o[0] * sc0; o0.y = o[1] * sc0;
            o1.x = o[2] * sc1; o1.y = o[3] * sc1;
            *(float2*)&Ob[(size_t)r0 * DMODEL + c] = o0;
            *(float2*)&Ob[(size_t)r1 * DMODEL + c] = o1;
        }
    }
}

// ============================================================
// residual + LayerNorm (unbiased std, eps added to std)
// ============================================================
__global__ void ln_kernel(const float* __restrict__ queries,
                          const float* __restrict__ gamma,
                          const float* __restrict__ beta,
                          float* __restrict__ out) {
    int row = blockIdx.x;
    int tid = threadIdx.x; // 128
    __shared__ float xs[DMODEL];
    __shared__ float rbuf[4];
    __shared__ float s_mean, s_rstd;
    const float* att = g_att + (size_t)row * DMODEL;
    const float* q   = queries + (size_t)row * DMODEL;

    float s = 0.f;
    for (int i = tid; i < DMODEL; i += 128) {
        float v = att[i] + q[i];
        xs[i] = v;
        s += v;
    }
    #pragma unroll
    for (int off = 16; off; off >>= 1) s += __shfl_xor_sync(0xffffffffu, s, off);
    if ((tid & 31) == 0) rbuf[tid >> 5] = s;
    __syncthreads();
    if (tid == 0) s_mean = (rbuf[0] + rbuf[1] + rbuf[2] + rbuf[3]) * (1.0f / DMODEL);
    __syncthreads();
    float mean = s_mean;
    float v2 = 0.f;
    for (int i = tid; i < DMODEL; i += 128) { float d = xs[i] - mean; v2 += d * d; }
    #pragma unroll
    for (int off = 16; off; off >>= 1) v2 += __shfl_xor_sync(0xffffffffu, v2, off);
    if ((tid & 31) == 0) rbuf[tid >> 5] = v2;
    __syncthreads();
    if (tid == 0) {
        float var = (rbuf[0] + rbuf[1] + rbuf[2] + rbuf[3]) * (1.0f / (DMODEL - 1));
        s_rstd = 1.0f / (sqrtf(var) + LN_EPS_F);
    }
    __syncthreads();
    float rstd = s_rstd;
    for (int i = tid; i < DMODEL; i += 128)
        out[(size_t)row * DMODEL + i] = gamma[i] * (xs[i] - mean) * rstd + beta[i];
}

// ============================================================
extern "C" void kernel_launch(void* const* d_in, const int* in_sizes, int n_in,
                              void* d_out, int out_size) {
    const float* queries = (const float*)d_in[0];
    const float* keys    = (const float*)d_in[1];
    const float* values  = (const float*)d_in[2];
    const float* Wq = (const float*)d_in[3];
    const float* bq = (const float*)d_in[4];
    const float* Wk = (const float*)d_in[5];
    const float* bk = (const float*)d_in[6];
    const float* Wv = (const float*)d_in[7];
    const float* bv = (const float*)d_in[8];
    const float* gamma = (const float*)d_in[9];
    const float* beta  = (const float*)d_in[10];
    float* out = (float*)d_out;

    convert_in_kernel<<<MROWS, 128>>>(queries, keys, values);
    convert_w_kernel<<<dim3(8, 8, 3), 256>>>(Wq, Wk, Wv);

    const int GSMEM = 4 * 128 * UPAD * (int)sizeof(uint32_t); // 73728 B
    cudaFuncSetAttribute(gemm_relu_bf16,
                         cudaFuncAttributeMaxDynamicSharedMemorySize, GSMEM);
    gemm_relu_bf16<<<dim3(DMODEL / 128, MROWS / 128, 3), 256, GSMEM>>>(bq, bk, bv);

    const int ASMEM = 128 * UPAD * (int)sizeof(uint32_t); // 18432 B
    cudaFuncSetAttribute(attn_bf16_kernel,
                         cudaFuncAttributeMaxDynamicSharedMemorySize, ASMEM);
    attn_bf16_kernel<<<dim3(SEQ / 128, NHEAD * BATCH), 256, ASMEM>>>();

    ln_kernel<<<MROWS, 128>>>(queries, gamma, beta, out);
}

// round 15
// speedup vs baseline: 1.2500x; 1.1889x over previous
#include <cuda_runtime.h>
#include <stdint.h>
#include <math.h>

#define BATCH 4
#define SEQ   2048
#define DMODEL 512
#define NHEAD 8
#define DHEAD 64
#define MROWS (BATCH*SEQ)          // 8192
#define DKU   (DMODEL/2)           // 256 uints (bf16 pairs) per row
#define NEG_INF_F (-4294967295.0f) // -2^32+1
#define LN_EPS_F 1e-8f
#define UPAD 36                    // padded smem row stride in uint32 (bank-clean)

// ---- scratch (no allocs allowed) ----
__device__ uint32_t g_inb[3u*MROWS*DKU];   // bf16-packed inputs q|k|v
__device__ uint32_t g_Wb[3u*DMODEL*DKU];   // bf16 W transposed [n][kpair], q|k|v
__device__ uint32_t g_Pq[MROWS*DKU];       // projected Q (bf16 pairs)
__device__ uint32_t g_Pk[MROWS*DKU];
__device__ uint32_t g_Pv[MROWS*DKU];
__device__ float    g_att[MROWS*DMODEL];
__device__ float    g_qmask[MROWS];
__device__ float    g_kmask[MROWS];

// pack two fp32 -> bf16x2 (lo in low half)
__device__ __forceinline__ uint32_t pack_bf16(float lo, float hi) {
    uint32_t r;
    asm("cvt.rn.bf16x2.f32 %0, %1, %2;" : "=r"(r) : "f"(hi), "f"(lo));
    return r;
}

__device__ __forceinline__ uint32_t mul_bf16x2(uint32_t a, uint32_t b) {
    uint32_t r;
    asm("mul.rn.bf16x2 %0, %1, %2;" : "=r"(r) : "r"(a), "r"(b));
    return r;
}

// D += A @ B  (m16n8k16 bf16, fp32 accum; A row-major, B col-major)
#define MMA_BF16(d, a, b0, b1)                                              \
    asm volatile(                                                           \
        "mma.sync.aligned.m16n8k16.row.col.f32.bf16.bf16.f32 "              \
        "{%0,%1,%2,%3}, {%4,%5,%6,%7}, {%8,%9}, {%0,%1,%2,%3};"             \
        : "+f"((d)[0]), "+f"((d)[1]), "+f"((d)[2]), "+f"((d)[3])            \
        : "r"((a)[0]), "r"((a)[1]), "r"((a)[2]), "r"((a)[3]),               \
          "r"(b0), "r"(b1))

#define LDSM4(r0, r1, r2, r3, addr)                                         \
    asm volatile("ldmatrix.sync.aligned.m8n8.x4.shared.b16 "                \
                 "{%0,%1,%2,%3}, [%4];"                                     \
                 : "=r"(r0), "=r"(r1), "=r"(r2), "=r"(r3) : "r"(addr))

#define LDSM4T(r0, r1, r2, r3, addr)                                        \
    asm volatile("ldmatrix.sync.aligned.m8n8.x4.trans.shared.b16 "          \
                 "{%0,%1,%2,%3}, [%4];"                                     \
                 : "=r"(r0), "=r"(r1), "=r"(r2), "=r"(r3) : "r"(addr))

__device__ __forceinline__ void cp16(void* s, const void* g) {
    uint32_t sa = (uint32_t)__cvta_generic_to_shared(s);
    asm volatile("cp.async.ca.shared.global [%0], [%1], 16;" :: "r"(sa), "l"(g));
}
#define CP_COMMIT() asm volatile("cp.async.commit_group;")
#define CP_WAIT1()  asm volatile("cp.async.wait_group 1;")

// ============================================================
// convert inputs fp32 -> bf16 pairs + row masks (fused)
// ============================================================
__global__ void convert_in_kernel(const float* __restrict__ q,
                                  const float* __restrict__ k,
                                  const float* __restrict__ v) {
    int row = blockIdx.x;
    int tid = threadIdx.x;
    size_t off = (size_t)row * DMODEL + tid * 4;
    size_t uoff = (size_t)row * DKU + tid * 2;

    float4 vq = *(const float4*)&q[off];
    float4 vk = *(const float4*)&k[off];
    float4 vv = *(const float4*)&v[off];
    uint2 pq, pk, pv;
    pq.x = pack_bf16(vq.x, vq.y); pq.y = pack_bf16(vq.z, vq.w);
    pk.x = pack_bf16(vk.x, vk.y); pk.y = pack_bf16(vk.z, vk.w);
    pv.x = pack_bf16(vv.x, vv.y); pv.y = pack_bf16(vv.z, vv.w);
    *(uint2*)&g_inb[uoff]                           = pq;
    *(uint2*)&g_inb[(size_t)MROWS * DKU + uoff]     = pk;
    *(uint2*)&g_inb[(size_t)2 * MROWS * DKU + uoff] = pv;

    float sq = vq.x + vq.y + vq.z + vq.w;
    float sk = vk.x + vk.y + vk.z + vk.w;
    #pragma unroll
    for (int o = 16; o; o >>= 1) {
        sq += __shfl_xor_sync(0xffffffffu, sq, o);
        sk += __shfl_xor_sync(0xffffffffu, sk, o);
    }
    __shared__ float bq[4], bk[4];
    if ((tid & 31) == 0) { bq[tid >> 5] = sq; bk[tid >> 5] = sk; }
    __syncthreads();
    if (tid == 0) {
        float tq = bq[0] + bq[1] + bq[2] + bq[3];
        float tk = bk[0] + bk[1] + bk[2] + bk[3];
        g_qmask[row] = (tq != 0.f) ? 1.f : 0.f;
        g_kmask[row] = (tk != 0.f) ? 1.f : 0.f;
    }
}

// ============================================================
// convert W -> transposed bf16 pairs: g_Wb[z][n][kpair]
// ============================================================
__global__ void convert_w_kernel(const float* __restrict__ Wq,
                                 const float* __restrict__ Wk,
                                 const float* __restrict__ Wv) {
    const float* W = (blockIdx.z == 0) ? Wq : (blockIdx.z == 1) ? Wk : Wv;
    __shared__ float T[64][65];   // T[n][k]
    int n0 = blockIdx.x * 64, k0 = blockIdx.y * 64;
    int tid = threadIdx.x;
    #pragma unroll
    for (int it = 0; it < 16; it++) {
        int lin = tid + it * 256;
        int r = lin >> 6, c = lin & 63;           // r=k, c=n
        T[c][r] = W[(size_t)(k0 + r) * DMODEL + n0 + c];
    }
    __syncthreads();
    uint32_t* out = g_Wb + (size_t)blockIdx.z * DMODEL * DKU;
    #pragma unroll
    for (int it = 0; it < 8; it++) {
        int lin = tid + it * 256;
        int n = lin >> 5, kp = lin & 31;
        out[(size_t)(n0 + n) * DKU + (k0 >> 1) + kp] =
            pack_bf16(T[n][2 * kp], T[n][2 * kp + 1]);
    }
}

// ============================================================
// fused projections: C = relu(A @ W + b), bf16 in/out, fp32 accum
// grid (N/128, M/128, 3), block 256, K-chunk 64, cp.async dbl-buffered
// ============================================================
__global__ void __launch_bounds__(256)
gemm_relu_bf16(const float* __restrict__ biasq,
               const float* __restrict__ biask,
               const float* __restrict__ biasv) {
    int z = blockIdx.z;
    const uint32_t* Ab = g_inb + (size_t)z * MROWS * DKU;
    const uint32_t* Wb = g_Wb + (size_t)z * DMODEL * DKU;
    const float* bias = (z == 0) ? biasq : (z == 1) ? biask : biasv;
    uint32_t* C = (z == 0) ? g_Pq : (z == 1) ? g_Pk : g_Pv;

    extern __shared__ uint32_t sm[];
    uint32_t* Abuf = sm;                    // 2 x 128 x UPAD
    uint32_t* Wbuf = sm + 2 * 128 * UPAD;   // 2 x 128 x UPAD

    int tid = threadIdx.x;
    int w = tid >> 5, lane = tid & 31;
    int g = lane >> 2, tg = lane & 3;
    int wm = w >> 1, wn = w & 1;
    int m0 = blockIdx.y * 128, n0 = blockIdx.x * 128;
    int mw = wm * 32;

    float acc[16][4];
    #pragma unroll
    for (int i = 0; i < 16; i++)
        #pragma unroll
        for (int j = 0; j < 4; j++) acc[i][j] = 0.f;

    auto stage = [&](int buf, int k0) {
        const uint32_t* Ag = Ab + (size_t)m0 * DKU + (k0 >> 1);
        const uint32_t* Wg = Wb + (size_t)n0 * DKU + (k0 >> 1);
        uint32_t* Ad = Abuf + buf * 128 * UPAD;
        uint32_t* Wd = Wbuf + buf * 128 * UPAD;
        #pragma unroll
        for (int it = 0; it < 4; it++) {
            int lin = tid + it * 256;
            int r = lin >> 3, c = (lin & 7) << 2;
            cp16(Ad + r * UPAD + c, Ag + (size_t)r * DKU + c);
            cp16(Wd + r * UPAD + c, Wg + (size_t)r * DKU + c);
        }
    };

    stage(0, 0);
    CP_COMMIT();

    for (int i = 0; i < 8; i++) {
        if (i + 1 < 8) stage((i + 1) & 1, (i + 1) * 64);
        CP_COMMIT();
        CP_WAIT1();
        __syncthreads();
        const uint32_t* Ap = Abuf + (i & 1) * 128 * UPAD;
        const uint32_t* Wp = Wbuf + (i & 1) * 128 * UPAD;
        #pragma unroll
        for (int ks = 0; ks < 4; ks++) {
            int cb = ks * 8 + tg;
            uint32_t a0[4], a1[4];
            a0[0] = Ap[(mw + g) * UPAD + cb];
            a0[1] = Ap[(mw + g + 8) * UPAD + cb];
            a0[2] = Ap[(mw + g) * UPAD + cb + 4];
            a0[3] = Ap[(mw + g + 8) * UPAD + cb + 4];
            a1[0] = Ap[(mw + 16 + g) * UPAD + cb];
            a1[1] = Ap[(mw + 24 + g) * UPAD + cb];
            a1[2] = Ap[(mw + 16 + g) * UPAD + cb + 4];
            a1[3] = Ap[(mw + 24 + g) * UPAD + cb + 4];
            #pragma unroll
            for (int nb = 0; nb < 8; nb++) {
                uint32_t b0 = Wp[(wn * 64 + nb * 8 + g) * UPAD + cb];
                uint32_t b1 = Wp[(wn * 64 + nb * 8 + g) * UPAD + cb + 4];
                MMA_BF16(acc[nb], a0, b0, b1);
                MMA_BF16(acc[8 + nb], a1, b0, b1);
            }
        }
        __syncthreads();
    }

    #pragma unroll
    for (int mt = 0; mt < 2; mt++) {
        int r0 = m0 + mw + mt * 16 + g;
        int r1 = r0 + 8;
        #pragma unroll
        for (int nb = 0; nb < 8; nb++) {
            int c = n0 + wn * 64 + nb * 8 + 2 * tg;
            float b0v = bias[c], b1v = bias[c + 1];
            const float* ac = acc[mt * 8 + nb];
            uint32_t cu = (c >> 1);
            C[(size_t)r0 * DKU + cu] =
                pack_bf16(fmaxf(ac[0] + b0v, 0.f), fmaxf(ac[1] + b1v, 0.f));
            C[(size_t)r1 * DKU + cu] =
                pack_bf16(fmaxf(ac[2] + b0v, 0.f), fmaxf(ac[3] + b1v, 0.f));
        }
    }
}

// ============================================================
// flash attention, bf16 m16n8k16 mma, ldmatrix(+trans) fragments,
// P kept in registers, cp.async double-buffered K/V/kmask.
// BQ=128 (8 warps x 16 q-rows), BK=64, dh=64
// grid: (SEQ/128, NHEAD*BATCH), block 256, 2 CTAs/SM
// dyn smem (uint32): 2 x { Kp[64][UPAD] | Vp[64][UPAD] }
// ============================================================
__global__ void __launch_bounds__(256, 2)
attn_bf16_kernel() {
    extern __shared__ uint32_t sm[];
    __shared__ float kmss[2][64];

    int tid = threadIdx.x;
    int w = tid >> 5, lane = tid & 31;
    int g = lane >> 2, tg = lane & 3;
    int l7 = lane & 7, qd = lane >> 3;
    int head = blockIdx.y >> 2, b = blockIdx.y & 3;
    int q0 = blockIdx.x * 128;
    int mw = w * 16;
    int hoff = head * 32;   // head offset in uints

    const uint32_t* Qb = g_Pq + (size_t)b * SEQ * DKU + hoff;
    const uint32_t* Kb = g_Pk + (size_t)b * SEQ * DKU + hoff;
    const uint32_t* Vb = g_Pv + (size_t)b * SEQ * DKU + hoff;

    uint32_t smb = (uint32_t)__cvta_generic_to_shared(sm);

    // ---- stage Q (pre-scaled by 1/8, exact) across buffer 0 region ----
    const uint32_t SCL = 0x3E003E00u;   // bf16x2 {0.125, 0.125}
    #pragma unroll
    for (int it = 0; it < 4; it++) {
        int lin = tid + it * 256;
        int r = lin >> 3, c = (lin & 7) << 2;
        uint4 v = *(const uint4*)&Qb[(size_t)(q0 + r) * DKU + c];
        v.x = mul_bf16x2(v.x, SCL); v.y = mul_bf16x2(v.y, SCL);
        v.z = mul_bf16x2(v.z, SCL); v.w = mul_bf16x2(v.w, SCL);
        *(uint4*)&sm[r * UPAD + c] = v;
    }
    __syncthreads();

    // A-type ldmatrix lane address (rows m, cols k)
    uint32_t qrow = mw + l7 + ((qd & 1) << 3);
    uint32_t qcol = (qd >> 1) << 2;
    uint32_t Qa[4][4];
    #pragma unroll
    for (int ks = 0; ks < 4; ks++)
        LDSM4(Qa[ks][0], Qa[ks][1], Qa[ks][2], Qa[ks][3],
              smb + (qrow * UPAD + ks * 8 + qcol) * 4);
    __syncthreads();   // Q region about to be overwritten by K/V staging

    // K (non-trans B): m0=row+0 col+0, m1=row+0 col+4, m2=row+8 col+0, m3=row+8 col+4
    uint32_t koff = ((l7 + ((qd >> 1) << 3)) * UPAD + ((qd & 1) << 2)) * 4;
    // V (trans B): m0=(k+0,n+0) m1=(k+8,n+0) m2=(k+0,n+4u) m3=(k+8,n+4u)
    uint32_t voff = ((l7 + ((qd & 1) << 3)) * UPAD + ((qd >> 1) << 2)) * 4;

    // cp.async staging of one k-tile into buffer buf
    auto stage = [&](int buf, int kt) {
        uint32_t* Kd = sm + buf * 2 * 64 * UPAD;
        uint32_t* Vd = Kd + 64 * UPAD;
        #pragma unroll
        for (int it = 0; it < 2; it++) {
            int lin = tid + it * 256;
            int r = lin >> 3, c = (lin & 7) << 2;
            cp16(Kd + r * UPAD + c, Kb + (size_t)(kt + r) * DKU + c);
            cp16(Vd + r * UPAD + c, Vb + (size_t)(kt + r) * DKU + c);
        }
        if (tid < 16) cp16(&kmss[buf][tid * 4], &g_kmask[b * SEQ + kt + tid * 4]);
    };

    float O[8][4];
    #pragma unroll
    for (int i = 0; i < 8; i++)
        #pragma unroll
        for (int j = 0; j < 4; j++) O[i][j] = 0.f;
    float mr0 = -3.0e38f, mr1 = -3.0e38f;
    float lr0 = 0.f, lr1 = 0.f;

    stage(0, 0);
    CP_COMMIT();

    for (int i = 0; i < SEQ / 64; i++) {
        if (i + 1 < SEQ / 64) stage((i + 1) & 1, (i + 1) * 64);
        CP_COMMIT();
        CP_WAIT1();
        __syncthreads();

        int buf = i & 1;
        uint32_t kfb = smb + (buf * 2 * 64 * UPAD) * 4 + koff;
        uint32_t vfb = smb + (buf * 2 * 64 * UPAD + 64 * UPAD) * 4 + voff;
        const float* kms = kmss[buf];

        // ---- S = (Q/8) @ K^T : per warp 16 x 64 ----
        float Sc[8][4];
        #pragma unroll
        for (int ii = 0; ii < 8; ii++)
            #pragma unroll
            for (int j = 0; j < 4; j++) Sc[ii][j] = 0.f;
        #pragma unroll
        for (int ks = 0; ks < 4; ks++) {
            #pragma unroll
            for (int nbp = 0; nbp < 4; nbp++) {
                uint32_t b0, b1, b2, b3;
                LDSM4(b0, b1, b2, b3, kfb + (nbp * 16 * UPAD + ks * 8) * 4);
                MMA_BF16(Sc[2 * nbp], Qa[ks], b0, b1);
                MMA_BF16(Sc[2 * nbp + 1], Qa[ks], b2, b3);
            }
        }

        // ---- key mask + running row max (2 rows/lane) ----
        float mx0 = -3.0e38f, mx1 = -3.0e38f;
        #pragma unroll
        for (int nb = 0; nb < 8; nb++) {
            int c = nb * 8 + 2 * tg;
            float km0 = kms[c], km1 = kms[c + 1];
            float* S = Sc[nb];
            S[0] = (km0 != 0.f) ? S[0] : NEG_INF_F;
            S[1] = (km1 != 0.f) ? S[1] : NEG_INF_F;
            S[2] = (km0 != 0.f) ? S[2] : NEG_INF_F;
            S[3] = (km1 != 0.f) ? S[3] : NEG_INF_F;
            mx0 = fmaxf(mx0, fmaxf(S[0], S[1]));
            mx1 = fmaxf(mx1, fmaxf(S[2], S[3]));
        }
        #pragma unroll
        for (int off = 1; off <= 2; off <<= 1) {
            mx0 = fmaxf(mx0, __shfl_xor_sync(0xffffffffu, mx0, off));
            mx1 = fmaxf(mx1, __shfl_xor_sync(0xffffffffu, mx1, off));
        }
        float mn0 = fmaxf(mr0, mx0), mn1 = fmaxf(mr1, mx1);
        float al0 = __expf(mr0 - mn0), al1 = __expf(mr1 - mn1);
        mr0 = mn0; mr1 = mn1;

        // ---- P = exp(S-m) packed straight into A-fragments ----
        uint32_t Pa[8][2];
        float s0 = 0.f, s1 = 0.f;
        #pragma unroll
        for (int nb = 0; nb < 8; nb++) {
            float* S = Sc[nb];
            float p0 = __expf(S[0] - mn0);
            float p1 = __expf(S[1] - mn0);
            float p2 = __expf(S[2] - mn1);
            float p3 = __expf(S[3] - mn1);
            s0 += p0 + p1;
            s1 += p2 + p3;
            Pa[nb][0] = pack_bf16(p0, p1);
            Pa[nb][1] = pack_bf16(p2, p3);
        }
        #pragma unroll
        for (int off = 1; off <= 2; off <<= 1) {
            s0 += __shfl_xor_sync(0xffffffffu, s0, off);
            s1 += __shfl_xor_sync(0xffffffffu, s1, off);
        }
        lr0 = lr0 * al0 + s0;
        lr1 = lr1 * al1 + s1;

        // rescale running O
        #pragma unroll
        for (int nb = 0; nb < 8; nb++) {
            float* o = O[nb];
            o[0] *= al0; o[1] *= al0;
            o[2] *= al1; o[3] *= al1;
        }

        // ---- O += P @ V  (V natural layout, trans-ldmatrix B-frags) ----
        #pragma unroll
        for (int j = 0; j < 4; j++) {    // key-blocks of 16
            uint32_t a[4];
            a[0] = Pa[2 * j][0];
            a[1] = Pa[2 * j][1];
            a[2] = Pa[2 * j + 1][0];
            a[3] = Pa[2 * j + 1][1];
            #pragma unroll
            for (int nbp = 0; nbp < 4; nbp++) {
                uint32_t b0, b1, b2, b3;
                LDSM4T(b0, b1, b2, b3, vfb + (j * 16 * UPAD + nbp * 8) * 4);
                MMA_BF16(O[2 * nbp], a, b0, b1);
                MMA_BF16(O[2 * nbp + 1], a, b2, b3);
            }
        }
        __syncthreads();   // all warps done with buf before restaging it
    }

    // ---- epilogue: query mask, 1/l, write fp32 ----
    float* Ob = g_att + (size_t)(b * SEQ + q0) * DMODEL + head * DHEAD;
    {
        int r0 = mw + g;
        int r1 = r0 + 8;
        float sc0 = g_qmask[b * SEQ + q0 + r0] / lr0;
        float sc1 = g_qmask[b * SEQ + q0 + r1] / lr1;
        #pragma unroll
        for (int nb = 0; nb < 8; nb++) {
            int c = nb * 8 + 2 * tg;
            const float* o = O[nb];
            float2 o0, o1;
            o0.x = o[0] * sc0; o0.y = o[1] * sc0;
            o1.x = o[2] * sc1; o1.y = o[3] * sc1;
            *(float2*)&Ob[(size_t)r0 * DMODEL + c] = o0;
            *(float2*)&Ob[(size_t)r1 * DMODEL + c] = o1;
        }
    }
}

// ============================================================
// residual + LayerNorm (unbiased std, eps added to std)
// ============================================================
__global__ void ln_kernel(const float* __restrict__ queries,
                          const float* __restrict__ gamma,
                          const float* __restrict__ beta,
                          float* __restrict__ out) {
    int row = blockIdx.x;
    int tid = threadIdx.x; // 128
    __shared__ float xs[DMODEL];
    __shared__ float rbuf[4];
    __shared__ float s_mean, s_rstd;
    const float* att = g_att + (size_t)row * DMODEL;
    const float* q   = queries + (size_t)row * DMODEL;

    float s = 0.f;
    for (int i = tid; i < DMODEL; i += 128) {
        float v = att[i] + q[i];
        xs[i] = v;
        s += v;
    }
    #pragma unroll
    for (int off = 16; off; off >>= 1) s += __shfl_xor_sync(0xffffffffu, s, off);
    if ((tid & 31) == 0) rbuf[tid >> 5] = s;
    __syncthreads();
    if (tid == 0) s_mean = (rbuf[0] + rbuf[1] + rbuf[2] + rbuf[3]) * (1.0f / DMODEL);
    __syncthreads();
    float mean = s_mean;
    float v2 = 0.f;
    for (int i = tid; i < DMODEL; i += 128) { float d = xs[i] - mean; v2 += d * d; }
    #pragma unroll
    for (int off = 16; off; off >>= 1) v2 += __shfl_xor_sync(0xffffffffu, v2, off);
    if ((tid & 31) == 0) rbuf[tid >> 5] = v2;
    __syncthreads();
    if (tid == 0) {
        float var = (rbuf[0] + rbuf[1] + rbuf[2] + rbuf[3]) * (1.0f / (DMODEL - 1));
        s_rstd = 1.0f / (sqrtf(var) + LN_EPS_F);
    }
    __syncthreads();
    float rstd = s_rstd;
    for (int i = tid; i < DMODEL; i += 128)
        out[(size_t)row * DMODEL + i] = gamma[i] * (xs[i] - mean) * rstd + beta[i];
}

// ============================================================
extern "C" void kernel_launch(void* const* d_in, const int* in_sizes, int n_in,
                              void* d_out, int out_size) {
    const float* queries = (const float*)d_in[0];
    const float* keys    = (const float*)d_in[1];
    const float* values  = (const float*)d_in[2];
    const float* Wq = (const float*)d_in[3];
    const float* bq = (const float*)d_in[4];
    const float* Wk = (const float*)d_in[5];
    const float* bk = (const float*)d_in[6];
    const float* Wv = (const float*)d_in[7];
    const float* bv = (const float*)d_in[8];
    const float* gamma = (const float*)d_in[9];
    const float* beta  = (const float*)d_in[10];
    float* out = (float*)d_out;

    convert_in_kernel<<<MROWS, 128>>>(queries, keys, values);
    convert_w_kernel<<<dim3(8, 8, 3), 256>>>(Wq, Wk, Wv);

    const int GSMEM = 4 * 128 * UPAD * (int)sizeof(uint32_t); // 73728 B
    cudaFuncSetAttribute(gemm_relu_bf16,
                         cudaFuncAttributeMaxDynamicSharedMemorySize, GSMEM);
    gemm_relu_bf16<<<dim3(DMODEL / 128, MROWS / 128, 3), 256, GSMEM>>>(bq, bk, bv);

    const int ASMEM = 4 * 64 * UPAD * (int)sizeof(uint32_t); // 36864 B
    cudaFuncSetAttribute(attn_bf16_kernel,
                         cudaFuncAttributeMaxDynamicSharedMemorySize, ASMEM);
    attn_bf16_kernel<<<dim3(SEQ / 128, NHEAD * BATCH), 256, ASMEM>>>();

    ln_kernel<<<MROWS, 128>>>(queries, gamma, beta, out);
}